// round 14
// baseline (speedup 1.0000x reference)
#include <cuda_runtime.h>
#include <cuda_bf16.h>
#include <cstdint>

// ConvSSM scan, spatial domain.
//   Phase 1: U_t = B (*) x_t for all (t,b,c) — parallel, scan-layout scratch.
//   Phase 2: h_t = A (*) h_{t-1} + U_t — 64 sequential steps. Each (b,c) chain
//            runs on a 2-CTA CLUSTER (128 CTAs total -> 2x the SMs):
//            rank r owns rows 32r..32r+31 (8 warps x 4 rows, lane = col pair).
//            Intra-CTA vertical halos: pairwise named barriers (linear chain).
//            Cross-CTA halo (one row-pair each way per step): DSMEM store via
//            mapa + double-buffered full/empty mbarrier pipeline with explicit
//            release.cluster arrives / acquire.cluster waits.
// (*) = circular conv on the 64x64 torus (== reference zero-padded FFT product).

#define NT 64
#define NB 2
#define NC 32
#define NH 32
#define NW 32
#define NBC 64
#define USLOTS 153          // 17*9  (l=0..16 col pair, widx=0..8 row group)
#define USLICE (USLOTS * 8)

__device__ __align__(16) float g_U[(size_t)(NT + 1) * NBC * USLICE];

typedef unsigned long long u64;

__device__ __forceinline__ u64 pk(float lo, float hi) {
    u64 r; asm("mov.b64 %0, {%1, %2};" : "=l"(r) : "f"(lo), "f"(hi)); return r;
}
__device__ __forceinline__ float2 unpk(u64 v) {
    float2 f; asm("mov.b64 {%0, %1}, %2;" : "=f"(f.x), "=f"(f.y) : "l"(v)); return f;
}
__device__ __forceinline__ u64 f2fma(u64 a, u64 b, u64 c) {
    u64 d; asm("fma.rn.f32x2 %0, %1, %2, %3;" : "=l"(d) : "l"(a), "l"(b), "l"(c));
    return d;
}
__device__ __forceinline__ void barpair(int id) {
    asm volatile("bar.sync %0, 64;" :: "r"(id) : "memory");
}
__device__ __forceinline__ uint32_t smem_u32(const void* p) {
    uint32_t a;
    asm("{ .reg .u64 t; cvta.to.shared.u64 t, %1; cvt.u32.u64 %0, t; }"
        : "=r"(a) : "l"(p));
    return a;
}
__device__ __forceinline__ uint32_t mapa_u32(uint32_t laddr, uint32_t rank) {
    uint32_t r;
    asm("mapa.shared::cluster.u32 %0, %1, %2;" : "=r"(r) : "r"(laddr), "r"(rank));
    return r;
}
__device__ __forceinline__ void mbar_wait(uint32_t mbar, int ph) {
    asm volatile(
        "{\n\t.reg .pred P;\n\t"
        "W%=:\n\t"
        "mbarrier.try_wait.parity.acquire.cluster.shared::cta.b64 P, [%0], %1, 0x989680;\n\t"
        "@P bra D%=;\n\t"
        "bra W%=;\n\t"
        "D%=:\n\t}"
        :: "r"(mbar), "r"(ph) : "memory");
}
// release at CLUSTER scope: orders prior DSMEM stores / SMEM reads before the
// arrival becomes visible to the peer (this was the R13 bug: default .cta scope).
__device__ __forceinline__ void mbar_arrive_remote(uint32_t raddr) {
    asm volatile("mbarrier.arrive.release.cluster.shared::cluster.b64 _, [%0];"
                 :: "r"(raddr) : "memory");
}
__device__ __forceinline__ void st_cluster_u64(uint32_t raddr, u64 v) {
    asm volatile("st.shared::cluster.u64 [%0], %1;" :: "r"(raddr), "l"(v) : "memory");
}
__device__ __forceinline__ void cluster_sync() {
    asm volatile("barrier.cluster.arrive.aligned;" ::: "memory");
    asm volatile("barrier.cluster.wait.aligned;" ::: "memory");
}

__device__ __forceinline__ void mkops(u64 P, int src, u64& O0, u64& O1, u64& O2) {
    u64 L = __shfl_sync(0xffffffffu, P, src);
    float2 Pf = unpk(P), Lf = unpk(L);
    O0 = P; O2 = L; O1 = pk(Lf.y, Pf.x);
}
__device__ __forceinline__ u64 cdy(const u64* A2, int dy, u64 O0, u64 O1, u64 O2, u64 acc) {
    acc = f2fma(A2[3 * dy + 0], O0, acc);
    acc = f2fma(A2[3 * dy + 1], O1, acc);
    acc = f2fma(A2[3 * dy + 2], O2, acc);
    return acc;
}

// ---------------------------------------------------------------------------
// Phase 1: U = B (*) x (zero-padded x), one CTA per (t,b,c) slice.
// ---------------------------------------------------------------------------
__global__ __launch_bounds__(192)
void u_precompute(const float* __restrict__ x, const float* __restrict__ Bk)
{
    __shared__ __align__(16) float xs[38 * 44];
    const int n   = blockIdx.x;           // n = t*NBC + bc
    const int c   = n & (NC - 1);
    const int tid = threadIdx.x;

    for (int i = tid; i < 38 * 44; i += 192) xs[i] = 0.0f;
    __syncthreads();

    const float2* xsl = (const float2*)(x + (size_t)n * (NH * NW));
    for (int i = tid; i < (NH * NW) / 2; i += 192) {
        const int r = i >> 4, c2 = (i & 15) * 2;
        float2 v = xsl[i];
        *(float2*)&xs[(r + 2) * 44 + c2 + 2] = v;
    }

    float Bw[9];
#pragma unroll
    for (int j = 0; j < 9; ++j) Bw[j] = Bk[c * 9 + j];
    __syncthreads();

    if (tid < USLOTS) {
        const int l = tid / 9;
        const int w = tid % 9;
        const int c0 = 2 * l;
        float o[4][2];
#pragma unroll
        for (int i = 0; i < 4; ++i) {
            const int r = 4 * w + i;
            o[i][0] = 0.f; o[i][1] = 0.f;
#pragma unroll
            for (int dy = 0; dy < 3; ++dy) {
                const float* rp = &xs[(r + 2 - dy) * 44 + c0 + 2];
#pragma unroll
                for (int dx = 0; dx < 3; ++dx) {
                    o[i][0] = fmaf(Bw[dy * 3 + dx], rp[-dx], o[i][0]);
                    o[i][1] = fmaf(Bw[dy * 3 + dx], rp[1 - dx], o[i][1]);
                }
            }
        }
        float* up = &g_U[(size_t)n * USLICE + tid * 8];
        *(float4*)(up)     = make_float4(o[0][0], o[0][1], o[1][0], o[1][1]);
        *(float4*)(up + 4) = make_float4(o[2][0], o[2][1], o[3][0], o[3][1]);
    }
}

// ---------------------------------------------------------------------------
// Phase 2: 2-CTA-cluster scan. 256 threads = 8 warps per CTA; grid = 2*NBC.
// ---------------------------------------------------------------------------
__global__ __launch_bounds__(256, 1) __cluster_dims__(2, 1, 1)
void convssm_scan(const float* __restrict__ Ak, float* __restrict__ out)
{
    __shared__ __align__(16) ulonglong2 halo[2][7][32];  // producer warp 0..6
    __shared__ __align__(16) ulonglong2 xb[2][32];       // cross-CTA halo bufs
    __shared__ __align__(8)  u64 mbar[4];  // full0, full1, empty0, empty1

    const int tid  = threadIdx.x;
    const int lane = tid & 31;
    const int w    = tid >> 5;
    uint32_t rank;
    asm("mov.u32 %0, %%cluster_ctarank;" : "=r"(rank));
    const uint32_t peer = rank ^ 1u;
    const int bc   = blockIdx.x >> 1;
    const int c    = bc & (NC - 1);
    const int src  = (lane + 31) & 31;
    const int widx = (int)rank * 8 + w;    // absolute row group, rows 4*widx..+3

    u64 A2[9];
#pragma unroll
    for (int j = 0; j < 9; ++j) { float a = Ak[c * 9 + j]; A2[j] = pk(a, a); }

    u64 h0 = 0ull, h1 = 0ull, h2 = 0ull, h3 = 0ull;

    for (int i = tid; i < 2 * 7 * 32; i += 256)
        (&halo[0][0][0])[i] = make_ulonglong2(0ull, 0ull);
    for (int i = tid; i < 2 * 32; i += 256)
        (&xb[0][0])[i] = make_ulonglong2(0ull, 0ull);
    if (tid == 0) {
#pragma unroll
        for (int j = 0; j < 4; ++j)
            asm volatile("mbarrier.init.shared.b64 [%0], %1;"
                         :: "r"(smem_u32(&mbar[j])), "r"(32) : "memory");
    }
    __syncthreads();
    cluster_sync();   // peer barriers/buffers initialized before any remote op

    // Precomputed local/remote addresses.
    const uint32_t mb_l  = smem_u32(&mbar[0]);
    const uint32_t mb_r  = mapa_u32(mb_l, peer);
    const uint32_t xb_r  = mapa_u32(smem_u32(&xb[0][0]), peer);

    // U stream (scan layout): slot (lane, widx), 8 floats.
    const bool ul   = (lane < 17) && (widx < 9);
    const float* up = g_U + (size_t)bc * USLICE + (lane * 9 + widx) * 8;
    const size_t ustep = (size_t)NBC * USLICE;

    u64 ua0, ua1, ua2, ua3;
    {
        float4 a = make_float4(0.f,0.f,0.f,0.f), b = a;
        if (ul) { a = *(const float4*)(up); b = *(const float4*)(up + 4); }
        ua0 = pk(a.x, a.y); ua1 = pk(a.z, a.w);
        ua2 = pk(b.x, b.y); ua3 = pk(b.z, b.w);
    }
    up += ustep;

    float* ob = out + (size_t)bc * (NH * NW) + (4 * widx) * NW + 2 * lane;
    const bool emits = (widx < 8) && (lane < 16);

    // mbarrier phase trackers (only warps 0 and 7 use them).
    int phf0 = 0, phf1 = 0;        // consumer full[b]
    int phe0 = 0, phe1 = 1;        // producer empty[b'] (b'=1 first use passes)

#pragma unroll 2
    for (int t = 0; t < NT; ++t) {
        const int pb = t & 1;

        // ---- acquire halo rows (h_{t-1} rows 4*widx-2, 4*widx-1) ----
        ulonglong2 hv;
        if (w == 0) {
            if (t > 0) {
                if (pb) { mbar_wait(mb_l + 8, phf1); phf1 ^= 1; }
                else    { mbar_wait(mb_l + 0, phf0); phf0 ^= 1; }
            }
            hv = xb[pb][lane];
            mbar_arrive_remote(mb_r + (2 + pb) * 8);   // free buffer for peer
        } else {
            hv = halo[pb][w - 1][lane];
        }

        u64 acc0 = ua0, acc1 = ua1, acc2 = ua2, acc3 = ua3;

        // Prefetch U_{t+1} (guard slice at t = NT-1).
        float4 na = make_float4(0.f,0.f,0.f,0.f), nb = na;
        if (ul) { na = *(const float4*)(up); nb = *(const float4*)(up + 4); }
        up += ustep;

        // ---- conv ----
        u64 O0, O1, O2;
        mkops(hv.x, src, O0, O1, O2);
        acc0 = cdy(A2, 2, O0, O1, O2, acc0);
        mkops(hv.y, src, O0, O1, O2);
        acc0 = cdy(A2, 1, O0, O1, O2, acc0);
        acc1 = cdy(A2, 2, O0, O1, O2, acc1);
        mkops(h0, src, O0, O1, O2);
        acc0 = cdy(A2, 0, O0, O1, O2, acc0);
        acc1 = cdy(A2, 1, O0, O1, O2, acc1);
        acc2 = cdy(A2, 2, O0, O1, O2, acc2);
        mkops(h1, src, O0, O1, O2);
        acc1 = cdy(A2, 0, O0, O1, O2, acc1);
        acc2 = cdy(A2, 1, O0, O1, O2, acc2);
        acc3 = cdy(A2, 2, O0, O1, O2, acc3);
        mkops(h2, src, O0, O1, O2);
        acc2 = cdy(A2, 0, O0, O1, O2, acc2);
        acc3 = cdy(A2, 1, O0, O1, O2, acc3);
        mkops(h3, src, O0, O1, O2);
        acc3 = cdy(A2, 0, O0, O1, O2, acc3);

        h0 = acc0; h1 = acc1; h2 = acc2; h3 = acc3;

        // ---- publish bottom pair ----
        if (w < 7) {
            halo[pb ^ 1][w][lane] = make_ulonglong2(acc2, acc3);
        } else if (t < NT - 1) {
            const int nb2 = pb ^ 1;
            if (nb2) { mbar_wait(mb_l + 24, phe1); phe1 ^= 1; }
            else     { mbar_wait(mb_l + 16, phe0); phe0 ^= 1; }
            const uint32_t dst = xb_r + (uint32_t)(nb2 * 32 + lane) * 16u;
            st_cluster_u64(dst,     acc2);
            st_cluster_u64(dst + 8, acc3);
            mbar_arrive_remote(mb_r + nb2 * 8);   // release.cluster: stores land first
        }

        // ---- emit ----
        if (emits) {
            float* o = ob + (size_t)t * (NBC * NH * NW);
            *(u64*)(o)          = acc0;
            *(u64*)(o + NW)     = acc1;
            *(u64*)(o + 2 * NW) = acc2;
            *(u64*)(o + 3 * NW) = acc3;
        }

        ua0 = pk(na.x, na.y); ua1 = pk(na.z, na.w);
        ua2 = pk(nb.x, nb.y); ua3 = pk(nb.z, nb.w);

        // ---- intra-CTA pairwise barriers (linear chain, increasing id) ----
        if (w > 0) barpair(w);
        if (w < 7) barpair(w + 1);
    }

    cluster_sync();   // keep smem alive for in-flight remote arrivals
}

extern "C" void kernel_launch(void* const* d_in, const int* in_sizes, int n_in,
                              void* d_out, int out_size) {
    const float* x  = (const float*)d_in[0];
    const float* Ak = (const float*)d_in[1];
    const float* Bk = (const float*)d_in[2];
    float* out = (float*)d_out;
    u_precompute<<<NT * NBC, 192>>>(x, Bk);
    convssm_scan<<<2 * NBC, 256>>>(Ak, out);
}

// round 15
// speedup vs baseline: 1.8193x; 1.8193x over previous
#include <cuda_runtime.h>
#include <cuda_bf16.h>
#include <cstdint>

// ConvSSM scan, spatial domain — scalar-register edition.
//   Phase 1: U_t = B (*) x_t for all (t,b,c) — parallel, scan-layout scratch.
//   Phase 2: h_t = A (*) h_{t-1} + U_t — 64 sequential steps, one CTA of 512
//            threads per (b,c) chain. Warp w owns rows 4w..4w+3, lane l owns
//            cols 2l,2l+1 as PLAIN FLOATS (no f32x2 packing -> no MOV tax).
//            Horizontal wrap via 2 float shfl per input row; vertical halo via
//            one float4 STS/LDS, double-buffered; one __syncthreads per step.
// (*) = circular conv on the 64x64 torus (== reference zero-padded FFT product).

#define NT 64
#define NB 2
#define NC 32
#define NH 32
#define NW 32
#define NBC 64
#define USLOTS 153          // 17*9  (l=0..16 col pair, w=0..8 row group)
#define USLICE (USLOTS * 8)

// +1 guard slice for unconditional distance-1 prefetch.
__device__ __align__(16) float g_U[(size_t)(NT + 1) * NBC * USLICE];

// ---------------------------------------------------------------------------
// Phase 1: U = B (*) x (zero-padded x), one CTA per (t,b,c) slice.
// Threads 0..152 compute the 8 floats scan-thread (l,w) reads.
// ---------------------------------------------------------------------------
__global__ __launch_bounds__(192)
void u_precompute(const float* __restrict__ x, const float* __restrict__ Bk)
{
    __shared__ __align__(16) float xs[38 * 44];   // idx = actual + 2, zero border
    const int n   = blockIdx.x;           // n = t*NBC + bc
    const int c   = n & (NC - 1);
    const int tid = threadIdx.x;

    for (int i = tid; i < 38 * 44; i += 192) xs[i] = 0.0f;
    __syncthreads();

    const float2* xsl = (const float2*)(x + (size_t)n * (NH * NW));
    for (int i = tid; i < (NH * NW) / 2; i += 192) {
        const int r = i >> 4, c2 = (i & 15) * 2;
        float2 v = xsl[i];
        *(float2*)&xs[(r + 2) * 44 + c2 + 2] = v;
    }

    float Bw[9];
#pragma unroll
    for (int j = 0; j < 9; ++j) Bw[j] = Bk[c * 9 + j];
    __syncthreads();

    if (tid < USLOTS) {
        const int l = tid / 9;            // col pair 0..16 -> cols 2l,2l+1
        const int w = tid % 9;            // row group -> rows 4w..4w+3
        const int c0 = 2 * l;
        float o[4][2];
#pragma unroll
        for (int i = 0; i < 4; ++i) {
            const int r = 4 * w + i;      // rows 34,35 compute to 0 naturally
            o[i][0] = 0.f; o[i][1] = 0.f;
#pragma unroll
            for (int dy = 0; dy < 3; ++dy) {
                const float* rp = &xs[(r + 2 - dy) * 44 + c0 + 2];
#pragma unroll
                for (int dx = 0; dx < 3; ++dx) {
                    o[i][0] = fmaf(Bw[dy * 3 + dx], rp[-dx], o[i][0]);
                    o[i][1] = fmaf(Bw[dy * 3 + dx], rp[1 - dx], o[i][1]);
                }
            }
        }
        float* up = &g_U[(size_t)n * USLICE + tid * 8];
        *(float4*)(up)     = make_float4(o[0][0], o[0][1], o[1][0], o[1][1]);
        *(float4*)(up + 4) = make_float4(o[2][0], o[2][1], o[3][0], o[3][1]);
    }
}

// ---------------------------------------------------------------------------
// Phase 2: scalar register-resident scan. 512 threads = 16 warps, 1 CTA/(b,c).
// ---------------------------------------------------------------------------
__global__ __launch_bounds__(512, 1)
void convssm_scan(const float* __restrict__ Ak, float* __restrict__ out)
{
    // halo[buf][w][lane] = {r(4w+2)c0, r(4w+2)c1, r(4w+3)c0, r(4w+3)c1}
    __shared__ __align__(16) float4 halo[2][16][32];

    const int tid  = threadIdx.x;
    const int lane = tid & 31;
    const int w    = tid >> 5;
    const int bc   = blockIdx.x;
    const int c    = bc & (NC - 1);
    const int src  = (lane + 31) & 31;     // circular left neighbor
    const int wm1  = (w + 15) & 15;        // warp above

    float A[9];
#pragma unroll
    for (int j = 0; j < 9; ++j) A[j] = Ak[c * 9 + j];

    // State h_{-1} = 0: s0[i]=col c0, s1[i]=col c1 for own row i (0..3).
    float s0[4] = {0.f, 0.f, 0.f, 0.f};
    float s1[4] = {0.f, 0.f, 0.f, 0.f};

    for (int i = tid; i < 2 * 16 * 32; i += 512)
        (&halo[0][0][0])[i] = make_float4(0.f, 0.f, 0.f, 0.f);

    // U stream (scan layout): slot (lane, w), 8 floats.
    const bool ul   = (lane < 17) && (w < 9);
    const float* up = g_U + (size_t)bc * USLICE + (lane * 9 + w) * 8;
    const size_t ustep = (size_t)NBC * USLICE;

    // Prefetch U_0: ua = rows 0,1 ; ub = rows 2,3 (c0,c1 interleaved).
    float4 ua = make_float4(0.f,0.f,0.f,0.f), ubv = ua;
    if (ul) { ua = *(const float4*)(up); ubv = *(const float4*)(up + 4); }
    up += ustep;

    float* ob = out + (size_t)bc * (NH * NW) + (4 * w) * NW + 2 * lane;
    const bool emits = (w < 8) && (lane < 16);

    __syncthreads();

#pragma unroll 2
    for (int t = 0; t < NT; ++t) {
        const int pb = t & 1;

        // Vertical halo rows (h_{t-1} rows 4w-2, 4w-1), one LDS.128.
        float4 hv = halo[pb][wm1][lane];

        // Input rows -2..3 as (c0, c1) scalar pairs.
        float i0[6], i1[6];
        i0[0] = hv.x; i1[0] = hv.y;      // row -2
        i0[1] = hv.z; i1[1] = hv.w;      // row -1
        i0[2] = s0[0]; i1[2] = s1[0];
        i0[3] = s0[1]; i1[3] = s1[1];
        i0[4] = s0[2]; i1[4] = s1[2];
        i0[5] = s0[3]; i1[5] = s1[3];

        // Left-neighbor cols (c0-2 = m2, c0-1 = m1) via float shfl.
        float m1[6], m2[6];
#pragma unroll
        for (int r = 0; r < 6; ++r) {
            m2[r] = __shfl_sync(0xffffffffu, i0[r], src);
            m1[r] = __shfl_sync(0xffffffffu, i1[r], src);
        }

        // acc = U_t
        float a0[4], a1[4];
        a0[0] = ua.x;  a1[0] = ua.y;
        a0[1] = ua.z;  a1[1] = ua.w;
        a0[2] = ubv.x; a1[2] = ubv.y;
        a0[3] = ubv.z; a1[3] = ubv.w;

        // Prefetch U_{t+1} (guard slice at t = NT-1).
        float4 na = make_float4(0.f,0.f,0.f,0.f), nbv = na;
        if (ul) { na = *(const float4*)(up); nbv = *(const float4*)(up + 4); }
        up += ustep;

        // acc += A (*) h_{t-1} : 72 scalar FFMA.
#pragma unroll
        for (int orow = 0; orow < 4; ++orow) {
#pragma unroll
            for (int dy = 0; dy < 3; ++dy) {
                const int ir = orow + 2 - dy;   // input row index 0..5
                a0[orow] = fmaf(A[dy * 3 + 0], i0[ir], a0[orow]);
                a0[orow] = fmaf(A[dy * 3 + 1], m1[ir], a0[orow]);
                a0[orow] = fmaf(A[dy * 3 + 2], m2[ir], a0[orow]);
                a1[orow] = fmaf(A[dy * 3 + 0], i1[ir], a1[orow]);
                a1[orow] = fmaf(A[dy * 3 + 1], i0[ir], a1[orow]);
                a1[orow] = fmaf(A[dy * 3 + 2], m1[ir], a1[orow]);
            }
        }

        // New state.
#pragma unroll
        for (int i = 0; i < 4; ++i) { s0[i] = a0[i]; s1[i] = a1[i]; }

        // Publish bottom-2 rows for the warp below (one STS.128).
        halo[pb ^ 1][w][lane] = make_float4(a0[2], a1[2], a0[3], a1[3]);

        // Emit cropped 32x32 output (4 STG.64).
        if (emits) {
            float* o = ob + (size_t)t * (NBC * NH * NW);
            *(float2*)(o)          = make_float2(a0[0], a1[0]);
            *(float2*)(o + NW)     = make_float2(a0[1], a1[1]);
            *(float2*)(o + 2 * NW) = make_float2(a0[2], a1[2]);
            *(float2*)(o + 3 * NW) = make_float2(a0[3], a1[3]);
        }

        // Commit U_{t+1}.
        ua = na; ubv = nbv;

        __syncthreads();
    }
}

extern "C" void kernel_launch(void* const* d_in, const int* in_sizes, int n_in,
                              void* d_out, int out_size) {
    const float* x  = (const float*)d_in[0];
    const float* Ak = (const float*)d_in[1];
    const float* Bk = (const float*)d_in[2];
    float* out = (float*)d_out;
    u_precompute<<<NT * NBC, 192>>>(x, Bk);
    convssm_scan<<<NBC, 512>>>(Ak, out);
}